// round 10
// baseline (speedup 1.0000x reference)
#include <cuda_runtime.h>
#include <cuda_fp16.h>

#define Bn 8
#define Qn 128
#define Kn 1024
#define Dn 256
#define Hn 256

// -------- scratch (no allocations allowed) --------
__device__ float  g_WqT[Dn * Hn];
__device__ float  g_WkT[Dn * Hn];
__device__ __half g_qprojH[Bn * Qn * Hn];
__device__ __half g_kprojH[Bn * Kn * Hn];
__device__ __half g_wvH[Hn];
__device__ float  g_scores[Bn * Qn * Kn];   // 4 MB; raw scores -> attn weights
__device__ int    g_valid[Bn];

__device__ __forceinline__ __half2 u2h(unsigned u) { __half2 h; *(unsigned*)&h = u; return h; }

// ============================================================
// Kernel 0: tiled transpose of W_q/W_k to [D][H] + w_v->half + valid decode.
// ============================================================
__global__ __launch_bounds__(256) void prep_kernel(const float* __restrict__ Wq,
                                                   const float* __restrict__ Wk,
                                                   const float* __restrict__ wv,
                                                   const void*  __restrict__ vlens) {
    __shared__ float tile[32][33];
    int m  = blockIdx.x & 1;
    int t  = blockIdx.x >> 1;          // 0..63
    int d0 = (t & 7) * 32;
    int h0 = (t >> 3) * 32;
    const float* src = m ? Wk : Wq;    // [H][D]
    float*       dst = m ? g_WkT : g_WqT;  // [D][H]
    int lx = threadIdx.x & 31, ly = threadIdx.x >> 5;

    #pragma unroll
    for (int i = 0; i < 32; i += 8)
        tile[ly + i][lx] = src[(size_t)(h0 + ly + i) * Dn + d0 + lx];
    __syncthreads();
    #pragma unroll
    for (int i = 0; i < 32; i += 8)
        dst[(size_t)(d0 + ly + i) * Hn + h0 + lx] = tile[lx][ly + i];

    if (blockIdx.x == 1)
        g_wvH[threadIdx.x] = __float2half_rn(wv[threadIdx.x]);

    if (blockIdx.x == 0 && threadIdx.x == 0) {
        const long long* p64 = (const long long*)vlens;
        const int*       p32 = (const int*)vlens;
        bool ok64 = true;
        for (int i = 0; i < Bn; i++) {
            long long v = p64[i];
            if (v < 0 || v > (long long)Kn) ok64 = false;
        }
        for (int i = 0; i < Bn; i++)
            g_valid[i] = ok64 ? (int)p64[i] : p32[i];
    }
}

// ============================================================
// Kernel 1: projections -> half outputs, scalar fp32 FFMA.
// grid = 288, block = 256; thread owns 4 h x 8 rows. Masked k-blocks exit.
// ============================================================
__global__ __launch_bounds__(256) void proj_kernel(
        const float* __restrict__ queries,
        const float* __restrict__ keys) {
    __shared__ float s_in[32][Dn];     // 32 KB

    int row0 = blockIdx.x * 32;
    bool is_q = (row0 < Bn * Qn);
    if (!is_q) {
        int rel = row0 - Bn * Qn;
        int b   = rel >> 10;
        int kr0 = rel & (Kn - 1);
        if (kr0 >= g_valid[b]) return;   // whole block masked
    }
    const float* in  = is_q ? (queries + (size_t)row0 * Dn)
                            : (keys + (size_t)(row0 - Bn * Qn) * Dn);
    __half* out      = is_q ? (g_qprojH + (size_t)row0 * Hn)
                            : (g_kprojH + (size_t)(row0 - Bn * Qn) * Hn);
    const float* WT  = is_q ? g_WqT : g_WkT;

    {   // cooperative load of 32 input rows (float4)
        const float4* in4 = (const float4*)in;
        float4* s4 = (float4*)&s_in[0][0];
        #pragma unroll
        for (int i = 0; i < 8; i++)
            s4[threadIdx.x + i * 256] = in4[threadIdx.x + i * 256];
    }
    __syncthreads();

    int hq = threadIdx.x & 63;     // h quad (4 h)
    int rg = threadIdx.x >> 6;     // row group (8 rows)

    float acc[8][4];
    #pragma unroll
    for (int r = 0; r < 8; r++)
        #pragma unroll
        for (int j = 0; j < 4; j++) acc[r][j] = 0.f;

    const float4* wt4 = (const float4*)WT;   // [d][64 quads]
    #pragma unroll 2
    for (int d4 = 0; d4 < 64; d4++) {
        float4 w[4];
        #pragma unroll
        for (int j = 0; j < 4; j++)
            w[j] = wt4[(size_t)(d4 * 4 + j) * 64 + hq];   // coalesced LDG.128
        #pragma unroll
        for (int r = 0; r < 8; r++) {
            float4 a = *(const float4*)&s_in[rg * 8 + r][d4 * 4];  // broadcast LDS.128
            #pragma unroll
            for (int j = 0; j < 4; j++) {
                float av = (&a.x)[j];
                acc[r][0] = fmaf(av, w[j].x, acc[r][0]);
                acc[r][1] = fmaf(av, w[j].y, acc[r][1]);
                acc[r][2] = fmaf(av, w[j].z, acc[r][2]);
                acc[r][3] = fmaf(av, w[j].w, acc[r][3]);
            }
        }
    }
    #pragma unroll
    for (int r = 0; r < 8; r++) {
        __half2 h01 = __floats2half2_rn(acc[r][0], acc[r][1]);
        __half2 h23 = __floats2half2_rn(acc[r][2], acc[r][3]);
        uint2 u = make_uint2(*(unsigned*)&h01, *(unsigned*)&h23);
        *(uint2*)&out[(size_t)(rg * 8 + r) * Hn + hq * 4] = u;   // STG.64 coalesced
    }
}

// ============================================================
// Kernel 2: scores via tanh.approx.f16x2. grid = 4096 blocks
// (b, qtile, k-chunk 32); early-exit masked. Lane = k; 8 warps = 8 q rows.
// ============================================================
__global__ __launch_bounds__(256, 6) void score_kernel() {
    __shared__ __half2 s_kT2[128 * 33];   // [h2][32 k + pad]
    __shared__ __half2 s_q2[8 * 128];
    __shared__ __half2 s_wv2[128];

    int kc = blockIdx.x & 31;
    int qt = (blockIdx.x >> 5) & 15;
    int b  = blockIdx.x >> 9;
    int L  = g_valid[b];
    int k0 = kc * 32;
    if (k0 >= L) return;               // uniform over block

    int t = threadIdx.x, w = t >> 5, l = t & 31;

    {   // transpose 32 k-rows (half) into s_kT2; conflict-free STS (stride 33)
        int kr = t >> 3, cg = t & 7;
        const uint4* src = (const uint4*)(g_kprojH + ((size_t)b * Kn + k0 + kr) * Hn);
        #pragma unroll
        for (int i = 0; i < 4; i++) {
            uint4 u = src[cg + i * 8];            // 8 halves = 4 h2
            int h2 = (cg + i * 8) * 4;
            s_kT2[(h2 + 0) * 33 + kr] = u2h(u.x);
            s_kT2[(h2 + 1) * 33 + kr] = u2h(u.y);
            s_kT2[(h2 + 2) * 33 + kr] = u2h(u.z);
            s_kT2[(h2 + 3) * 33 + kr] = u2h(u.w);
        }
    }
    {   // q tile: 8 rows x 512 B = 256 uint4
        const uint4* src = (const uint4*)(g_qprojH + ((size_t)b * Qn + qt * 8) * Hn);
        ((uint4*)s_q2)[t] = src[t];
    }
    if (t < 32) ((uint4*)s_wv2)[t] = ((const uint4*)g_wvH)[t];
    __syncthreads();

    const uint4* q4 = (const uint4*)(s_q2 + (size_t)w * 128);
    const uint4* w4 = (const uint4*)s_wv2;
    float accx = 0.f, accy = 0.f;

    #pragma unroll 8
    for (int i = 0; i < 32; i++) {          // 8 h per iter
        uint4 qu = q4[i];                   // broadcast LDS.128 (4 h2)
        uint4 wu = w4[i];                   // broadcast LDS.128
        const __half2* kp = &s_kT2[(size_t)(i * 4) * 33 + l];
        unsigned x0, x1, x2, x3, t0, t1, t2, t3;
        __half2 h;
        h = __hadd2(u2h(qu.x), kp[0 * 33]); x0 = *(unsigned*)&h;
        h = __hadd2(u2h(qu.y), kp[1 * 33]); x1 = *(unsigned*)&h;
        h = __hadd2(u2h(qu.z), kp[2 * 33]); x2 = *(unsigned*)&h;
        h = __hadd2(u2h(qu.w), kp[3 * 33]); x3 = *(unsigned*)&h;
        asm("tanh.approx.f16x2 %0, %1;" : "=r"(t0) : "r"(x0));
        asm("tanh.approx.f16x2 %0, %1;" : "=r"(t1) : "r"(x1));
        asm("tanh.approx.f16x2 %0, %1;" : "=r"(t2) : "r"(x2));
        asm("tanh.approx.f16x2 %0, %1;" : "=r"(t3) : "r"(x3));
        __half2 p0 = __hmul2(u2h(wu.x), u2h(t0));
        __half2 p1 = __hmul2(u2h(wu.y), u2h(t1));
        __half2 p2 = __hmul2(u2h(wu.z), u2h(t2));
        __half2 p3 = __hmul2(u2h(wu.w), u2h(t3));
        __half2 s = __hadd2(__hadd2(p0, p1), __hadd2(p2, p3));
        float2 f = __half22float2(s);       // flush every 8 h -> fp32
        accx += f.x;
        accy += f.y;
    }
    float s = accx + accy;
    int kk = k0 + l;
    if (kk < L)
        g_scores[((size_t)b * Qn + qt * 8 + w) * Kn + kk] = s;   // coalesced STG
}

// ============================================================
// Kernel 3: masked softmax in place on g_scores -> attn weights.
// grid = 512; block = 256 (4 warps per q row). Vectorized float4 I/O.
// Full row written (zeros beyond valid); L==0 -> uniform 1/1024.
// ============================================================
__global__ __launch_bounds__(256) void softmax_kernel() {
    __shared__ float s_max[8];
    __shared__ float s_sum[8];

    int t = threadIdx.x, w = t >> 5, l = t & 31;
    int r   = w >> 2;                       // row within block
    int row = blockIdx.x * 2 + r;           // global (b*Qn + q)
    int b   = row >> 7;
    int L   = g_valid[b];
    float* gs = g_scores + (size_t)row * Kn;
    int base = (w & 3) * 256 + l * 8;       // 8 consecutive per lane

    float4 v0 = *(const float4*)(gs + base);
    float4 v1 = *(const float4*)(gs + base + 4);
    float vals[8] = {v0.x, v0.y, v0.z, v0.w, v1.x, v1.y, v1.z, v1.w};
    float m = -3.4e38f;
    #pragma unroll
    for (int i = 0; i < 8; i++) {
        if (base + i >= L) vals[i] = -1e9f;   // garbage beyond L -> masked
        m = fmaxf(m, vals[i]);
    }
    #pragma unroll
    for (int o = 16; o > 0; o >>= 1)
        m = fmaxf(m, __shfl_xor_sync(0xffffffffu, m, o));
    if (l == 0) s_max[w] = m;
    __syncthreads();
    m = fmaxf(fmaxf(s_max[r * 4 + 0], s_max[r * 4 + 1]),
              fmaxf(s_max[r * 4 + 2], s_max[r * 4 + 3]));

    float sum = 0.f;
    #pragma unroll
    for (int i = 0; i < 8; i++) {
        float e = __expf(vals[i] - m);
        vals[i] = e;
        sum += e;
    }
    #pragma unroll
    for (int o = 16; o > 0; o >>= 1)
        sum += __shfl_xor_sync(0xffffffffu, sum, o);
    if (l == 0) s_sum[w] = sum;
    __syncthreads();
    float inv = 1.f / (s_sum[r * 4 + 0] + s_sum[r * 4 + 1] +
                       s_sum[r * 4 + 2] + s_sum[r * 4 + 3]);
    *(float4*)(gs + base)     = make_float4(vals[0] * inv, vals[1] * inv,
                                            vals[2] * inv, vals[3] * inv);
    *(float4*)(gs + base + 4) = make_float4(vals[4] * inv, vals[5] * inv,
                                            vals[6] * inv, vals[7] * inv);
}

// ============================================================
// Kernel 4: out = attn @ V — latency-optimized.
// grid = B*32*4 = 1024 blocks (b, q-tile of 4, d-chunk of 64); block = 256.
// Thread = (dl 0..63, k-slice 0..3); k unrolled x8 (MLP 8).
// All k bounds multiples of 8; attn==0 beyond L makes padding exact.
// smem 16 KB -> high occupancy; partials reuse attn smem after sync.
// ============================================================
__global__ __launch_bounds__(256, 6) void av_kernel(
        const float* __restrict__ values,
        float* __restrict__ out) {
    __shared__ float s_attn[4][Kn];       // 16 KB (attn -> partials)

    int dc = blockIdx.x & 3;
    int qt = (blockIdx.x >> 2) & 31;      // 32 tiles of 4 q rows
    int b  = blockIdx.x >> 7;
    int L  = g_valid[b];
    int kEff = (L == 0) ? Kn : L;
    int t = threadIdx.x;

    {   // stage 4 attn rows (16 KB) coalesced: 1024 float4, 4 per thread
        const float4* src = (const float4*)(g_scores + ((size_t)(b * Qn + qt * 4)) * Kn);
        float4* dst = (float4*)&s_attn[0][0];
        #pragma unroll
        for (int i = 0; i < 4; i++)
            dst[t + i * 256] = src[t + i * 256];
    }
    __syncthreads();

    int dl = t & 63;                 // d within chunk
    int ks = t >> 6;                 // k-slice 0..3
    const float* vb = values + (size_t)b * Kn * Dn + dc * 64 + dl;

    int kLim = (kEff + 7) & ~7;                   // <= 1024
    int per  = (((kLim >> 2) + 7) & ~7);          // per-slice span, multiple of 8
    int kb   = ks * per;
    int ke   = min(kb + per, kLim);

    float acc0 = 0.f, acc1 = 0.f, acc2 = 0.f, acc3 = 0.f;

    for (int k = kb; k < ke; k += 8) {
        float v[8];
        #pragma unroll
        for (int j = 0; j < 8; j++)               // 8 LDGs batched: MLP 8
            v[j] = vb[(size_t)(k + j) * Dn];
        #pragma unroll
        for (int j = 0; j < 8; j += 4) {
            float4 a0 = *(const float4*)&s_attn[0][k + j];   // broadcast LDS.128
            float4 a1 = *(const float4*)&s_attn[1][k + j];
            float4 a2 = *(const float4*)&s_attn[2][k + j];
            float4 a3 = *(const float4*)&s_attn[3][k + j];
            acc0 = fmaf(a0.x, v[j+0], acc0); acc0 = fmaf(a0.y, v[j+1], acc0);
            acc0 = fmaf(a0.z, v[j+2], acc0); acc0 = fmaf(a0.w, v[j+3], acc0);
            acc1 = fmaf(a1.x, v[j+0], acc1); acc1 = fmaf(a1.y, v[j+1], acc1);
            acc1 = fmaf(a1.z, v[j+2], acc1); acc1 = fmaf(a1.w, v[j+3], acc1);
            acc2 = fmaf(a2.x, v[j+0], acc2); acc2 = fmaf(a2.y, v[j+1], acc2);
            acc2 = fmaf(a2.z, v[j+2], acc2); acc2 = fmaf(a2.w, v[j+3], acc2);
            acc3 = fmaf(a3.x, v[j+0], acc3); acc3 = fmaf(a3.y, v[j+1], acc3);
            acc3 = fmaf(a3.z, v[j+2], acc3); acc3 = fmaf(a3.w, v[j+3], acc3);
        }
    }

    __syncthreads();                       // all attn reads done
    float* part = &s_attn[0][0];           // reuse: [ks 4][qq 4][dl 64]
    part[((ks * 4 + 0) << 6) + dl] = acc0;
    part[((ks * 4 + 1) << 6) + dl] = acc1;
    part[((ks * 4 + 2) << 6) + dl] = acc2;
    part[((ks * 4 + 3) << 6) + dl] = acc3;
    __syncthreads();

    {   // 256 outputs: thread -> (qq = t>>6, dl)
        int qq  = t >> 6;
        int dl2 = t & 63;
        float s = part[((0 * 4 + qq) << 6) + dl2] + part[((1 * 4 + qq) << 6) + dl2] +
                  part[((2 * 4 + qq) << 6) + dl2] + part[((3 * 4 + qq) << 6) + dl2];
        out[((size_t)(b * Qn + qt * 4 + qq)) * Dn + dc * 64 + dl2] = s;
    }
}

// ============================================================
extern "C" void kernel_launch(void* const* d_in, const int* in_sizes, int n_in,
                              void* d_out, int out_size) {
    const float* queries = (const float*)d_in[0];
    const float* keys    = (const float*)d_in[1];
    const float* values  = (const float*)d_in[2];
    const float* Wq      = (const float*)d_in[3];
    const float* Wk      = (const float*)d_in[4];
    const float* wv      = (const float*)d_in[5];
    const void*  vlens   =               d_in[6];
    float* out = (float*)d_out;

    prep_kernel<<<128, 256>>>(Wq, Wk, wv, vlens);
    proj_kernel<<<(Bn * Qn + Bn * Kn) / 32, 256>>>(queries, keys);
    score_kernel<<<Bn * 16 * 32, 256>>>();
    softmax_kernel<<<Bn * Qn / 2, 256>>>();
    av_kernel<<<Bn * 32 * 4, 256>>>(values, out);
}

// round 11
// speedup vs baseline: 1.1110x; 1.1110x over previous
#include <cuda_runtime.h>
#include <cuda_fp16.h>

#define Bn 8
#define Qn 128
#define Kn 1024
#define Dn 256
#define Hn 256

// -------- scratch (no allocations allowed) --------
__device__ float  g_WqT[Dn * Hn];
__device__ float  g_WkT[Dn * Hn];
__device__ __half g_qprojH[Bn * Qn * Hn];
__device__ __half g_kprojH[Bn * Kn * Hn];
__device__ __half g_wvH[Hn];
__device__ float  g_scores[Bn * Qn * Kn];   // 4 MB; raw scores -> attn weights
__device__ int    g_valid[Bn];

__device__ __forceinline__ __half2 u2h(unsigned u) { __half2 h; *(unsigned*)&h = u; return h; }

// ============================================================
// Kernel 0: tiled transpose of W_q/W_k to [D][H] + w_v->half + valid decode.
// ============================================================
__global__ __launch_bounds__(256) void prep_kernel(const float* __restrict__ Wq,
                                                   const float* __restrict__ Wk,
                                                   const float* __restrict__ wv,
                                                   const void*  __restrict__ vlens) {
    __shared__ float tile[32][33];
    int m  = blockIdx.x & 1;
    int t  = blockIdx.x >> 1;          // 0..63
    int d0 = (t & 7) * 32;
    int h0 = (t >> 3) * 32;
    const float* src = m ? Wk : Wq;    // [H][D]
    float*       dst = m ? g_WkT : g_WqT;  // [D][H]
    int lx = threadIdx.x & 31, ly = threadIdx.x >> 5;

    #pragma unroll
    for (int i = 0; i < 32; i += 8)
        tile[ly + i][lx] = src[(size_t)(h0 + ly + i) * Dn + d0 + lx];
    __syncthreads();
    #pragma unroll
    for (int i = 0; i < 32; i += 8)
        dst[(size_t)(d0 + ly + i) * Hn + h0 + lx] = tile[lx][ly + i];

    if (blockIdx.x == 1)
        g_wvH[threadIdx.x] = __float2half_rn(wv[threadIdx.x]);

    if (blockIdx.x == 0 && threadIdx.x == 0) {
        const long long* p64 = (const long long*)vlens;
        const int*       p32 = (const int*)vlens;
        bool ok64 = true;
        for (int i = 0; i < Bn; i++) {
            long long v = p64[i];
            if (v < 0 || v > (long long)Kn) ok64 = false;
        }
        for (int i = 0; i < Bn; i++)
            g_valid[i] = ok64 ? (int)p64[i] : p32[i];
    }
}

// ============================================================
// Kernel 1: projections -> half outputs, scalar fp32 FFMA.
// grid = 288, block = 256; thread owns 4 h x 8 rows. Masked k-blocks exit.
// ============================================================
__global__ __launch_bounds__(256) void proj_kernel(
        const float* __restrict__ queries,
        const float* __restrict__ keys) {
    __shared__ float s_in[32][Dn];     // 32 KB

    int row0 = blockIdx.x * 32;
    bool is_q = (row0 < Bn * Qn);
    if (!is_q) {
        int rel = row0 - Bn * Qn;
        int b   = rel >> 10;
        int kr0 = rel & (Kn - 1);
        if (kr0 >= g_valid[b]) return;   // whole block masked
    }
    const float* in  = is_q ? (queries + (size_t)row0 * Dn)
                            : (keys + (size_t)(row0 - Bn * Qn) * Dn);
    __half* out      = is_q ? (g_qprojH + (size_t)row0 * Hn)
                            : (g_kprojH + (size_t)(row0 - Bn * Qn) * Hn);
    const float* WT  = is_q ? g_WqT : g_WkT;

    {   // cooperative load of 32 input rows (float4)
        const float4* in4 = (const float4*)in;
        float4* s4 = (float4*)&s_in[0][0];
        #pragma unroll
        for (int i = 0; i < 8; i++)
            s4[threadIdx.x + i * 256] = in4[threadIdx.x + i * 256];
    }
    __syncthreads();

    int hq = threadIdx.x & 63;     // h quad (4 h)
    int rg = threadIdx.x >> 6;     // row group (8 rows)

    float acc[8][4];
    #pragma unroll
    for (int r = 0; r < 8; r++)
        #pragma unroll
        for (int j = 0; j < 4; j++) acc[r][j] = 0.f;

    const float4* wt4 = (const float4*)WT;   // [d][64 quads]
    #pragma unroll 2
    for (int d4 = 0; d4 < 64; d4++) {
        float4 w[4];
        #pragma unroll
        for (int j = 0; j < 4; j++)
            w[j] = wt4[(size_t)(d4 * 4 + j) * 64 + hq];   // coalesced LDG.128
        #pragma unroll
        for (int r = 0; r < 8; r++) {
            float4 a = *(const float4*)&s_in[rg * 8 + r][d4 * 4];  // broadcast LDS.128
            #pragma unroll
            for (int j = 0; j < 4; j++) {
                float av = (&a.x)[j];
                acc[r][0] = fmaf(av, w[j].x, acc[r][0]);
                acc[r][1] = fmaf(av, w[j].y, acc[r][1]);
                acc[r][2] = fmaf(av, w[j].z, acc[r][2]);
                acc[r][3] = fmaf(av, w[j].w, acc[r][3]);
            }
        }
    }
    #pragma unroll
    for (int r = 0; r < 8; r++) {
        __half2 h01 = __floats2half2_rn(acc[r][0], acc[r][1]);
        __half2 h23 = __floats2half2_rn(acc[r][2], acc[r][3]);
        uint2 u = make_uint2(*(unsigned*)&h01, *(unsigned*)&h23);
        *(uint2*)&out[(size_t)(rg * 8 + r) * Hn + hq * 4] = u;   // STG.64 coalesced
    }
}

// ============================================================
// Kernel 2: scores via tanh.approx.f16x2. grid = 4096 blocks
// (b, qtile, k-chunk 32); early-exit masked. Lane = k; 8 warps = 8 q rows.
// ============================================================
__global__ __launch_bounds__(256, 6) void score_kernel() {
    __shared__ __half2 s_kT2[128 * 33];   // [h2][32 k + pad]
    __shared__ __half2 s_q2[8 * 128];
    __shared__ __half2 s_wv2[128];

    int kc = blockIdx.x & 31;
    int qt = (blockIdx.x >> 5) & 15;
    int b  = blockIdx.x >> 9;
    int L  = g_valid[b];
    int k0 = kc * 32;
    if (k0 >= L) return;               // uniform over block

    int t = threadIdx.x, w = t >> 5, l = t & 31;

    {   // transpose 32 k-rows (half) into s_kT2; conflict-free STS (stride 33)
        int kr = t >> 3, cg = t & 7;
        const uint4* src = (const uint4*)(g_kprojH + ((size_t)b * Kn + k0 + kr) * Hn);
        #pragma unroll
        for (int i = 0; i < 4; i++) {
            uint4 u = src[cg + i * 8];            // 8 halves = 4 h2
            int h2 = (cg + i * 8) * 4;
            s_kT2[(h2 + 0) * 33 + kr] = u2h(u.x);
            s_kT2[(h2 + 1) * 33 + kr] = u2h(u.y);
            s_kT2[(h2 + 2) * 33 + kr] = u2h(u.z);
            s_kT2[(h2 + 3) * 33 + kr] = u2h(u.w);
        }
    }
    {   // q tile: 8 rows x 512 B = 256 uint4
        const uint4* src = (const uint4*)(g_qprojH + ((size_t)b * Qn + qt * 8) * Hn);
        ((uint4*)s_q2)[t] = src[t];
    }
    if (t < 32) ((uint4*)s_wv2)[t] = ((const uint4*)g_wvH)[t];
    __syncthreads();

    const uint4* q4 = (const uint4*)(s_q2 + (size_t)w * 128);
    const uint4* w4 = (const uint4*)s_wv2;
    float accx = 0.f, accy = 0.f;

    #pragma unroll 8
    for (int i = 0; i < 32; i++) {          // 8 h per iter
        uint4 qu = q4[i];                   // broadcast LDS.128 (4 h2)
        uint4 wu = w4[i];                   // broadcast LDS.128
        const __half2* kp = &s_kT2[(size_t)(i * 4) * 33 + l];
        unsigned x0, x1, x2, x3, t0, t1, t2, t3;
        __half2 h;
        h = __hadd2(u2h(qu.x), kp[0 * 33]); x0 = *(unsigned*)&h;
        h = __hadd2(u2h(qu.y), kp[1 * 33]); x1 = *(unsigned*)&h;
        h = __hadd2(u2h(qu.z), kp[2 * 33]); x2 = *(unsigned*)&h;
        h = __hadd2(u2h(qu.w), kp[3 * 33]); x3 = *(unsigned*)&h;
        asm("tanh.approx.f16x2 %0, %1;" : "=r"(t0) : "r"(x0));
        asm("tanh.approx.f16x2 %0, %1;" : "=r"(t1) : "r"(x1));
        asm("tanh.approx.f16x2 %0, %1;" : "=r"(t2) : "r"(x2));
        asm("tanh.approx.f16x2 %0, %1;" : "=r"(t3) : "r"(x3));
        __half2 p0 = __hmul2(u2h(wu.x), u2h(t0));
        __half2 p1 = __hmul2(u2h(wu.y), u2h(t1));
        __half2 p2 = __hmul2(u2h(wu.z), u2h(t2));
        __half2 p3 = __hmul2(u2h(wu.w), u2h(t3));
        __half2 s = __hadd2(__hadd2(p0, p1), __hadd2(p2, p3));
        float2 f = __half22float2(s);       // flush every 8 h -> fp32
        accx += f.x;
        accy += f.y;
    }
    float s = accx + accy;
    int kk = k0 + l;
    if (kk < L)
        g_scores[((size_t)b * Qn + qt * 8 + w) * Kn + kk] = s;   // coalesced STG
}

// ============================================================
// Kernel 3: masked softmax in place on g_scores -> attn weights.
// grid = 512; block = 256 (4 warps per q row). Vectorized float4 I/O.
// Full row written (zeros beyond valid); L==0 -> uniform 1/1024.
// ============================================================
__global__ __launch_bounds__(256) void softmax_kernel() {
    __shared__ float s_max[8];
    __shared__ float s_sum[8];

    int t = threadIdx.x, w = t >> 5, l = t & 31;
    int r   = w >> 2;                       // row within block
    int row = blockIdx.x * 2 + r;           // global (b*Qn + q)
    int b   = row >> 7;
    int L   = g_valid[b];
    float* gs = g_scores + (size_t)row * Kn;
    int base = (w & 3) * 256 + l * 8;       // 8 consecutive per lane

    float4 v0 = *(const float4*)(gs + base);
    float4 v1 = *(const float4*)(gs + base + 4);
    float vals[8] = {v0.x, v0.y, v0.z, v0.w, v1.x, v1.y, v1.z, v1.w};
    float m = -3.4e38f;
    #pragma unroll
    for (int i = 0; i < 8; i++) {
        if (base + i >= L) vals[i] = -1e9f;   // garbage beyond L -> masked
        m = fmaxf(m, vals[i]);
    }
    #pragma unroll
    for (int o = 16; o > 0; o >>= 1)
        m = fmaxf(m, __shfl_xor_sync(0xffffffffu, m, o));
    if (l == 0) s_max[w] = m;
    __syncthreads();
    m = fmaxf(fmaxf(s_max[r * 4 + 0], s_max[r * 4 + 1]),
              fmaxf(s_max[r * 4 + 2], s_max[r * 4 + 3]));

    float sum = 0.f;
    #pragma unroll
    for (int i = 0; i < 8; i++) {
        float e = __expf(vals[i] - m);
        vals[i] = e;
        sum += e;
    }
    #pragma unroll
    for (int o = 16; o > 0; o >>= 1)
        sum += __shfl_xor_sync(0xffffffffu, sum, o);
    if (l == 0) s_sum[w] = sum;
    __syncthreads();
    float inv = 1.f / (s_sum[r * 4 + 0] + s_sum[r * 4 + 1] +
                       s_sum[r * 4 + 2] + s_sum[r * 4 + 3]);
    *(float4*)(gs + base)     = make_float4(vals[0] * inv, vals[1] * inv,
                                            vals[2] * inv, vals[3] * inv);
    *(float4*)(gs + base + 4) = make_float4(vals[4] * inv, vals[5] * inv,
                                            vals[6] * inv, vals[7] * inv);
}

// ============================================================
// Kernel 4: out = attn @ V — q-reuse maximized (V L2 traffic halved vs R7).
// grid = B*8*4 = 256 blocks (b, q-tile of 16, d-chunk of 64); block = 256.
// Dynamic smem 64 KB: attn tile [16][1024] f32, reused for partials.
// Thread = (dl 0..63, k-slice 0..3); k batched x8 (MLP 8).
// All k bounds multiples of 8; attn==0 beyond L makes padding exact.
// ============================================================
__global__ __launch_bounds__(256) void av_kernel(
        const float* __restrict__ values,
        float* __restrict__ out) {
    extern __shared__ float s_dyn[];       // 64 KB: [16][Kn] attn -> partials

    int dc = blockIdx.x & 3;
    int qt = (blockIdx.x >> 2) & 7;        // 8 tiles of 16 q rows
    int b  = blockIdx.x >> 5;
    int L  = g_valid[b];
    int kEff = (L == 0) ? Kn : L;
    int t = threadIdx.x;

    {   // stage 16 attn rows (64 KB) coalesced: 4096 float4, 16 per thread
        const float4* src = (const float4*)(g_scores + ((size_t)(b * Qn + qt * 16)) * Kn);
        float4* dst = (float4*)s_dyn;
        #pragma unroll
        for (int i = 0; i < 16; i++)
            dst[t + i * 256] = src[t + i * 256];
    }
    __syncthreads();

    int dl = t & 63;                 // d within chunk
    int ks = t >> 6;                 // k-slice 0..3
    const float* vb = values + (size_t)b * Kn * Dn + dc * 64 + dl;

    int kLim = (kEff + 7) & ~7;                   // <= 1024
    int per  = (((kLim >> 2) + 7) & ~7);          // per-slice span, multiple of 8
    int kb   = ks * per;
    int ke   = min(kb + per, kLim);

    float acc[16];
    #pragma unroll
    for (int qq = 0; qq < 16; qq++) acc[qq] = 0.f;

    for (int k = kb; k < ke; k += 8) {
        float v[8];
        #pragma unroll
        for (int j = 0; j < 8; j++)               // 8 LDGs batched: MLP 8
            v[j] = vb[(size_t)(k + j) * Dn];
        #pragma unroll
        for (int j = 0; j < 8; j += 4) {
            #pragma unroll
            for (int qq = 0; qq < 16; qq++) {
                float4 a = *(const float4*)&s_dyn[qq * Kn + k + j];  // broadcast LDS.128
                acc[qq] = fmaf(a.x, v[j + 0], acc[qq]);
                acc[qq] = fmaf(a.y, v[j + 1], acc[qq]);
                acc[qq] = fmaf(a.z, v[j + 2], acc[qq]);
                acc[qq] = fmaf(a.w, v[j + 3], acc[qq]);
            }
        }
    }

    __syncthreads();                       // all attn reads done
    float* part = s_dyn;                   // reuse: [ks 4][qq 16][dl 64] = 16 KB
    #pragma unroll
    for (int qq = 0; qq < 16; qq++)
        part[((ks * 16 + qq) << 6) + dl] = acc[qq];
    __syncthreads();

    #pragma unroll
    for (int idx = t; idx < 1024; idx += 256) {   // 16 q x 64 d outputs
        int qq  = idx >> 6;
        int dl2 = idx & 63;
        float s = part[((0 * 16 + qq) << 6) + dl2] + part[((1 * 16 + qq) << 6) + dl2] +
                  part[((2 * 16 + qq) << 6) + dl2] + part[((3 * 16 + qq) << 6) + dl2];
        out[((size_t)(b * Qn + qt * 16 + qq)) * Dn + dc * 64 + dl2] = s;
    }
}

// ============================================================
extern "C" void kernel_launch(void* const* d_in, const int* in_sizes, int n_in,
                              void* d_out, int out_size) {
    const float* queries = (const float*)d_in[0];
    const float* keys    = (const float*)d_in[1];
    const float* values  = (const float*)d_in[2];
    const float* Wq      = (const float*)d_in[3];
    const float* Wk      = (const float*)d_in[4];
    const float* wv      = (const float*)d_in[5];
    const void*  vlens   =               d_in[6];
    float* out = (float*)d_out;

    static bool attr_done = false;
    if (!attr_done) {
        cudaFuncSetAttribute(av_kernel,
                             cudaFuncAttributeMaxDynamicSharedMemorySize, 16 * Kn * 4);
        attr_done = true;
    }

    prep_kernel<<<128, 256>>>(Wq, Wk, wv, vlens);
    proj_kernel<<<(Bn * Qn + Bn * Kn) / 32, 256>>>(queries, keys);
    score_kernel<<<Bn * 16 * 32, 256>>>();
    softmax_kernel<<<Bn * Qn / 2, 256>>>();
    av_kernel<<<Bn * 8 * 4, 256, 16 * Kn * 4>>>(values, out);
}

// round 13
// speedup vs baseline: 1.3311x; 1.1981x over previous
#include <cuda_runtime.h>
#include <cuda_fp16.h>

#define Bn 8
#define Qn 128
#define Kn 1024
#define Dn 256
#define Hn 256

// -------- scratch (no allocations allowed) --------
__device__ __half g_qprojH[Bn * Qn * Hn];
__device__ __half g_kprojH[Bn * Kn * Hn];
__device__ __half g_wvH[Hn];
__device__ float  g_scores[Bn * Qn * Kn];   // 4 MB; raw scores -> attn weights
__device__ int    g_valid[Bn];

__device__ __forceinline__ __half2 u2h(unsigned u) { __half2 h; *(unsigned*)&h = u; return h; }
__device__ __forceinline__ unsigned h2u(__half2 h) { return *(unsigned*)&h; }

// ============================================================
// Kernel 0: tiny prep — w_v -> half, valid_lens decode. grid = 1.
// ============================================================
__global__ __launch_bounds__(256) void prep_kernel(const float* __restrict__ wv,
                                                   const void*  __restrict__ vlens) {
    g_wvH[threadIdx.x] = __float2half_rn(wv[threadIdx.x]);
    if (threadIdx.x == 0) {
        const long long* p64 = (const long long*)vlens;
        const int*       p32 = (const int*)vlens;
        bool ok64 = true;
        for (int i = 0; i < Bn; i++) {
            long long v = p64[i];
            if (v < 0 || v > (long long)Kn) ok64 = false;
        }
        for (int i = 0; i < Bn; i++)
            g_valid[i] = ok64 ? (int)p64[i] : p32[i];
    }
}

// ============================================================
// Kernel 1: projections on the TENSOR pipe (HMMA m16n8k16 f16->f32).
// out[row][h] = sum_d in[row][d] * W[h][d]; W native [H][D] rows are the
// k-vectors of a col-major B fragment -> no transpose needed.
// Block: 64 rows x 256 h, K=256 in 4 chunks of 64.
// 8 warps = 4 row-groups(16) x 2 h-halves(128). Masked k-blocks exit early.
// grid = (1024 + 8192)/64 = 144, block = 256.
// ============================================================
__global__ __launch_bounds__(256) void proj_kernel(
        const float* __restrict__ queries,
        const float* __restrict__ keys,
        const float* __restrict__ Wq,
        const float* __restrict__ Wk) {
    __shared__ __half A_s[64 * 72];    // 9216 B  [row][d+pad]
    __shared__ __half B_s[256 * 72];   // 36864 B [h][d+pad]

    int row0 = blockIdx.x * 64;
    bool is_q = (row0 < Bn * Qn);
    if (!is_q) {
        int rel = row0 - Bn * Qn;
        int b   = rel >> 10;
        int kr0 = rel & (Kn - 1);
        if (kr0 >= g_valid[b]) return;   // whole block masked
    }
    const float* in = is_q ? (queries + (size_t)row0 * Dn)
                           : (keys + (size_t)(row0 - Bn * Qn) * Dn);
    const float* W  = is_q ? Wq : Wk;
    __half* out     = is_q ? (g_qprojH + (size_t)row0 * Hn)
                           : (g_kprojH + (size_t)(row0 - Bn * Qn) * Hn);

    int t = threadIdx.x, w = t >> 5, lane = t & 31;
    int g = lane >> 2, tg = lane & 3;
    int rw0 = (w >> 1) * 16;           // warp row base
    int h0w = (w & 1) * 128;           // warp h base

    float c[16][4];
    #pragma unroll
    for (int nt = 0; nt < 16; nt++)
        #pragma unroll
        for (int j = 0; j < 4; j++) c[nt][j] = 0.f;

    for (int chunk = 0; chunk < 4; chunk++) {
        int d0 = chunk * 64;
        __syncthreads();   // previous chunk's frags consumed

        {   // stage A: 64 rows x 64 d, f32 -> f16.  thread: row t>>2, quarter t&3
            int r = t >> 2, l4 = t & 3;
            const float4* src = (const float4*)(in + (size_t)r * Dn + d0);
            #pragma unroll
            for (int j = 0; j < 4; j++) {
                float4 v = src[l4 + j * 4];
                uint2 u = make_uint2(h2u(__floats2half2_rn(v.x, v.y)),
                                     h2u(__floats2half2_rn(v.z, v.w)));
                *(uint2*)&A_s[r * 72 + (l4 + j * 4) * 4] = u;
            }
        }
        {   // stage B: 256 h x 64 d, thread t = h (per-lane contiguous row read)
            const float4* srcW = (const float4*)(W + (size_t)t * Dn + d0);
            #pragma unroll
            for (int j = 0; j < 16; j++) {
                float4 v = srcW[j];
                uint2 u = make_uint2(h2u(__floats2half2_rn(v.x, v.y)),
                                     h2u(__floats2half2_rn(v.z, v.w)));
                *(uint2*)&B_s[t * 72 + j * 4] = u;
            }
        }
        __syncthreads();

        #pragma unroll
        for (int ks = 0; ks < 4; ks++) {
            int kb = ks * 16;
            unsigned a0 = *(const unsigned*)&A_s[(rw0 + g)     * 72 + kb + tg * 2];
            unsigned a1 = *(const unsigned*)&A_s[(rw0 + g + 8) * 72 + kb + tg * 2];
            unsigned a2 = *(const unsigned*)&A_s[(rw0 + g)     * 72 + kb + tg * 2 + 8];
            unsigned a3 = *(const unsigned*)&A_s[(rw0 + g + 8) * 72 + kb + tg * 2 + 8];
            #pragma unroll
            for (int nt = 0; nt < 16; nt++) {
                const __half* bp = &B_s[(h0w + nt * 8 + g) * 72 + kb + tg * 2];
                unsigned b0 = *(const unsigned*)bp;
                unsigned b1 = *(const unsigned*)(bp + 8);
                asm volatile(
                    "mma.sync.aligned.m16n8k16.row.col.f32.f16.f16.f32 "
                    "{%0,%1,%2,%3}, {%4,%5,%6,%7}, {%8,%9}, {%0,%1,%2,%3};"
                    : "+f"(c[nt][0]), "+f"(c[nt][1]), "+f"(c[nt][2]), "+f"(c[nt][3])
                    : "r"(a0), "r"(a1), "r"(a2), "r"(a3), "r"(b0), "r"(b1));
            }
        }
    }

    #pragma unroll
    for (int nt = 0; nt < 16; nt++) {
        int col = h0w + nt * 8 + tg * 2;
        *(unsigned*)&out[(size_t)(rw0 + g)     * Hn + col] =
            h2u(__floats2half2_rn(c[nt][0], c[nt][1]));
        *(unsigned*)&out[(size_t)(rw0 + g + 8) * Hn + col] =
            h2u(__floats2half2_rn(c[nt][2], c[nt][3]));
    }
}

// ============================================================
// Kernel 2: scores via tanh.approx.f16x2. grid = 4096 blocks
// (b, qtile, k-chunk 32); early-exit masked. Lane = k; 8 warps = 8 q rows.
// ============================================================
__global__ __launch_bounds__(256, 6) void score_kernel() {
    __shared__ __half2 s_kT2[128 * 33];   // [h2][32 k + pad]
    __shared__ __half2 s_q2[8 * 128];
    __shared__ __half2 s_wv2[128];

    int kc = blockIdx.x & 31;
    int qt = (blockIdx.x >> 5) & 15;
    int b  = blockIdx.x >> 9;
    int L  = g_valid[b];
    int k0 = kc * 32;
    if (k0 >= L) return;               // uniform over block

    int t = threadIdx.x, w = t >> 5, l = t & 31;

    {   // transpose 32 k-rows (half) into s_kT2; conflict-free STS (stride 33)
        int kr = t >> 3, cg = t & 7;
        const uint4* src = (const uint4*)(g_kprojH + ((size_t)b * Kn + k0 + kr) * Hn);
        #pragma unroll
        for (int i = 0; i < 4; i++) {
            uint4 u = src[cg + i * 8];            // 8 halves = 4 h2
            int h2 = (cg + i * 8) * 4;
            s_kT2[(h2 + 0) * 33 + kr] = u2h(u.x);
            s_kT2[(h2 + 1) * 33 + kr] = u2h(u.y);
            s_kT2[(h2 + 2) * 33 + kr] = u2h(u.z);
            s_kT2[(h2 + 3) * 33 + kr] = u2h(u.w);
        }
    }
    {   // q tile: 8 rows x 512 B = 256 uint4
        const uint4* src = (const uint4*)(g_qprojH + ((size_t)b * Qn + qt * 8) * Hn);
        ((uint4*)s_q2)[t] = src[t];
    }
    if (t < 32) ((uint4*)s_wv2)[t] = ((const uint4*)g_wvH)[t];
    __syncthreads();

    const uint4* q4 = (const uint4*)(s_q2 + (size_t)w * 128);
    const uint4* w4 = (const uint4*)s_wv2;
    float accx = 0.f, accy = 0.f;

    #pragma unroll 8
    for (int i = 0; i < 32; i++) {          // 8 h per iter
        uint4 qu = q4[i];                   // broadcast LDS.128 (4 h2)
        uint4 wu = w4[i];                   // broadcast LDS.128
        const __half2* kp = &s_kT2[(size_t)(i * 4) * 33 + l];
        unsigned x0, x1, x2, x3, t0, t1, t2, t3;
        __half2 h;
        h = __hadd2(u2h(qu.x), kp[0 * 33]); x0 = *(unsigned*)&h;
        h = __hadd2(u2h(qu.y), kp[1 * 33]); x1 = *(unsigned*)&h;
        h = __hadd2(u2h(qu.z), kp[2 * 33]); x2 = *(unsigned*)&h;
        h = __hadd2(u2h(qu.w), kp[3 * 33]); x3 = *(unsigned*)&h;
        asm("tanh.approx.f16x2 %0, %1;" : "=r"(t0) : "r"(x0));
        asm("tanh.approx.f16x2 %0, %1;" : "=r"(t1) : "r"(x1));
        asm("tanh.approx.f16x2 %0, %1;" : "=r"(t2) : "r"(x2));
        asm("tanh.approx.f16x2 %0, %1;" : "=r"(t3) : "r"(x3));
        __half2 p0 = __hmul2(u2h(wu.x), u2h(t0));
        __half2 p1 = __hmul2(u2h(wu.y), u2h(t1));
        __half2 p2 = __hmul2(u2h(wu.z), u2h(t2));
        __half2 p3 = __hmul2(u2h(wu.w), u2h(t3));
        __half2 s = __hadd2(__hadd2(p0, p1), __hadd2(p2, p3));
        float2 f = __half22float2(s);       // flush every 8 h -> fp32
        accx += f.x;
        accy += f.y;
    }
    float s = accx + accy;
    int kk = k0 + l;
    if (kk < L)
        g_scores[((size_t)b * Qn + qt * 8 + w) * Kn + kk] = s;   // coalesced STG
}

// ============================================================
// Kernel 3: masked softmax in place on g_scores -> attn weights.
// grid = 512; block = 256 (4 warps per q row). Vectorized float4 I/O.
// Full row written (zeros beyond valid); L==0 -> uniform 1/1024.
// ============================================================
__global__ __launch_bounds__(256) void softmax_kernel() {
    __shared__ float s_max[8];
    __shared__ float s_sum[8];

    int t = threadIdx.x, w = t >> 5, l = t & 31;
    int r   = w >> 2;                       // row within block
    int row = blockIdx.x * 2 + r;           // global (b*Qn + q)
    int b   = row >> 7;
    int L   = g_valid[b];
    float* gs = g_scores + (size_t)row * Kn;
    int base = (w & 3) * 256 + l * 8;       // 8 consecutive per lane

    float4 v0 = *(const float4*)(gs + base);
    float4 v1 = *(const float4*)(gs + base + 4);
    float vals[8] = {v0.x, v0.y, v0.z, v0.w, v1.x, v1.y, v1.z, v1.w};
    float m = -3.4e38f;
    #pragma unroll
    for (int i = 0; i < 8; i++) {
        if (base + i >= L) vals[i] = -1e9f;   // garbage beyond L -> masked
        m = fmaxf(m, vals[i]);
    }
    #pragma unroll
    for (int o = 16; o > 0; o >>= 1)
        m = fmaxf(m, __shfl_xor_sync(0xffffffffu, m, o));
    if (l == 0) s_max[w] = m;
    __syncthreads();
    m = fmaxf(fmaxf(s_max[r * 4 + 0], s_max[r * 4 + 1]),
              fmaxf(s_max[r * 4 + 2], s_max[r * 4 + 3]));

    float sum = 0.f;
    #pragma unroll
    for (int i = 0; i < 8; i++) {
        float e = __expf(vals[i] - m);
        vals[i] = e;
        sum += e;
    }
    #pragma unroll
    for (int o = 16; o > 0; o >>= 1)
        sum += __shfl_xor_sync(0xffffffffu, sum, o);
    if (l == 0) s_sum[w] = sum;
    __syncthreads();
    float inv = 1.f / (s_sum[r * 4 + 0] + s_sum[r * 4 + 1] +
                       s_sum[r * 4 + 2] + s_sum[r * 4 + 3]);
    *(float4*)(gs + base)     = make_float4(vals[0] * inv, vals[1] * inv,
                                            vals[2] * inv, vals[3] * inv);
    *(float4*)(gs + base + 4) = make_float4(vals[4] * inv, vals[5] * inv,
                                            vals[6] * inv, vals[7] * inv);
}

// ============================================================
// Kernel 4: out = attn @ V — R7 tiling (the measured optimum) + MLP-8 k-batching.
// grid = B*16*4 = 512 (b, q-tile of 8, d-chunk of 64); block = 256.
// Thread = (dl 0..63, k-slice 0..3); all k bounds multiples of 8
// (attn exactly 0 beyond L makes padding exact).
// ============================================================
__global__ __launch_bounds__(256) void av_kernel(
        const float* __restrict__ values,
        float* __restrict__ out) {
    __shared__ float s_attn[8][Kn];       // 32 KB
    __shared__ float s_part[4][8][64];    // 8 KB

    int dc = blockIdx.x & 3;
    int qt = (blockIdx.x >> 2) & 15;
    int b  = blockIdx.x >> 6;
    int L  = g_valid[b];
    int kEff = (L == 0) ? Kn : L;
    int t = threadIdx.x;

    {   // stage 8 attn rows coalesced
        const float4* src = (const float4*)(g_scores + ((size_t)(b * Qn + qt * 8)) * Kn);
        float4* dst = (float4*)&s_attn[0][0];
        #pragma unroll
        for (int i = 0; i < 8; i++)
            dst[t + i * 256] = src[t + i * 256];
    }
    __syncthreads();

    int dl = t & 63;                 // d within chunk
    int ks = t >> 6;                 // k-slice 0..3
    const float* vb = values + (size_t)b * Kn * Dn + dc * 64 + dl;

    int kLim = (kEff + 7) & ~7;
    int per  = (((kLim >> 2) + 7) & ~7);       // per-slice span, multiple of 8
    int kb   = ks * per;
    int ke   = min(kb + per, kLim);

    float acc[8];
    #pragma unroll
    for (int qq = 0; qq < 8; qq++) acc[qq] = 0.f;

    for (int k = kb; k < ke; k += 8) {
        float v[8];
        #pragma unroll
        for (int j = 0; j < 8; j++)               // 8 LDGs batched: MLP 8
            v[j] = vb[(size_t)(k + j) * Dn];
        #pragma unroll
        for (int j = 0; j < 8; j += 4) {
            #pragma unroll
            for (int qq = 0; qq < 8; qq++) {
                float4 a = *(const float4*)&s_attn[qq][k + j];   // broadcast LDS.128
                acc[qq] = fmaf(a.x, v[j + 0], acc[qq]);
                acc[qq] = fmaf(a.y, v[j + 1], acc[qq]);
                acc[qq] = fmaf(a.z, v[j + 2], acc[qq]);
                acc[qq] = fmaf(a.w, v[j + 3], acc[qq]);
            }
        }
    }

    #pragma unroll
    for (int qq = 0; qq < 8; qq++) s_part[ks][qq][dl] = acc[qq];
    __syncthreads();

    {
        int qq  = t >> 6;                 // reuse 256 threads: 4 slices x 64 d... 
        // 512 outputs: 8 q x 64 d; two per thread
        for (int idx = t; idx < 512; idx += 256) {
            int q2  = idx >> 6;
            int dl2 = idx & 63;
            float s = s_part[0][q2][dl2] + s_part[1][q2][dl2] +
                      s_part[2][q2][dl2] + s_part[3][q2][dl2];
            out[((size_t)(b * Qn + qt * 8 + q2)) * Dn + dc * 64 + dl2] = s;
        }
        (void)qq;
    }
}

// ============================================================
extern "C" void kernel_launch(void* const* d_in, const int* in_sizes, int n_in,
                              void* d_out, int out_size) {
    const float* queries = (const float*)d_in[0];
    const float* keys    = (const float*)d_in[1];
    const float* values  = (const float*)d_in[2];
    const float* Wq      = (const float*)d_in[3];
    const float* Wk      = (const float*)d_in[4];
    const float* wv      = (const float*)d_in[5];
    const void*  vlens   =               d_in[6];
    float* out = (float*)d_out;

    prep_kernel<<<1, 256>>>(wv, vlens);
    proj_kernel<<<(Bn * Qn + Bn * Kn) / 64, 256>>>(queries, keys, Wq, Wk);
    score_kernel<<<Bn * 16 * 32, 256>>>();
    softmax_kernel<<<Bn * Qn / 2, 256>>>();
    av_kernel<<<Bn * 16 * 4, 256>>>(values, out);
}

// round 17
// speedup vs baseline: 1.4125x; 1.0611x over previous
#include <cuda_runtime.h>
#include <cuda_fp16.h>

#define Bn 8
#define Qn 128
#define Kn 1024
#define Dn 256
#define Hn 256

// -------- scratch (no allocations allowed) --------
__device__ __half g_qprojH[Bn * Qn * Hn];
__device__ __half g_kprojH[Bn * Kn * Hn];
__device__ float  g_scores[Bn * Qn * Kn];   // 4 MB; holds exp(score), 0 when masked
__device__ int    g_valid_unused[Bn];       // kept for ABI stability; unused

__device__ __forceinline__ __half2 u2h(unsigned u) { __half2 h; *(unsigned*)&h = u; return h; }
__device__ __forceinline__ unsigned h2u(__half2 h) { return *(unsigned*)&h; }

// Inline valid_lens decode (int64 vs int32 sniff; ~20 instr, runs per block).
__device__ __forceinline__ int decode_valid(const void* vlens, int b) {
    const long long* p64 = (const long long*)vlens;
    const int*       p32 = (const int*)vlens;
    bool ok64 = true;
    #pragma unroll
    for (int i = 0; i < Bn; i++) {
        long long v = p64[i];
        if (v < 0 || v > (long long)Kn) ok64 = false;
    }
    return ok64 ? (int)p64[b] : p32[b];
}

// ============================================================
// Kernel 1: projections on the TENSOR pipe (HMMA m16n8k16 f16->f32).
// out[row][h] = sum_d in[row][d] * W[h][d]; W native [H][D] rows are the
// k-vectors of a col-major B fragment -> no transpose needed.
// Block: 64 rows x 256 h, K=256 in 4 chunks of 64. Masked k-blocks exit.
// grid = (1024 + 8192)/64 = 144, block = 256.
// ============================================================
__global__ __launch_bounds__(256) void proj_kernel(
        const float* __restrict__ queries,
        const float* __restrict__ keys,
        const float* __restrict__ Wq,
        const float* __restrict__ Wk,
        const void*  __restrict__ vlens) {
    __shared__ __half A_s[64 * 72];    // 9216 B  [row][d+pad]
    __shared__ __half B_s[256 * 72];   // 36864 B [h][d+pad]

    int row0 = blockIdx.x * 64;
    bool is_q = (row0 < Bn * Qn);
    if (!is_q) {
        int rel = row0 - Bn * Qn;
        int b   = rel >> 10;
        int kr0 = rel & (Kn - 1);
        if (kr0 >= decode_valid(vlens, b)) return;   // whole block masked
    }
    const float* in = is_q ? (queries + (size_t)row0 * Dn)
                           : (keys + (size_t)(row0 - Bn * Qn) * Dn);
    const float* W  = is_q ? Wq : Wk;
    __half* out     = is_q ? (g_qprojH + (size_t)row0 * Hn)
                           : (g_kprojH + (size_t)(row0 - Bn * Qn) * Hn);

    int t = threadIdx.x, w = t >> 5, lane = t & 31;
    int g = lane >> 2, tg = lane & 3;
    int rw0 = (w >> 1) * 16;           // warp row base
    int h0w = (w & 1) * 128;           // warp h base

    float c[16][4];
    #pragma unroll
    for (int nt = 0; nt < 16; nt++)
        #pragma unroll
        for (int j = 0; j < 4; j++) c[nt][j] = 0.f;

    for (int chunk = 0; chunk < 4; chunk++) {
        int d0 = chunk * 64;
        __syncthreads();   // previous chunk's frags consumed

        {   // stage A: 64 rows x 64 d, f32 -> f16.  thread: row t>>2, quarter t&3
            int r = t >> 2, l4 = t & 3;
            const float4* src = (const float4*)(in + (size_t)r * Dn + d0);
            #pragma unroll
            for (int j = 0; j < 4; j++) {
                float4 v = src[l4 + j * 4];
                uint2 u = make_uint2(h2u(__floats2half2_rn(v.x, v.y)),
                                     h2u(__floats2half2_rn(v.z, v.w)));
                *(uint2*)&A_s[r * 72 + (l4 + j * 4) * 4] = u;
            }
        }
        {   // stage B: 256 h x 64 d, thread t = h (per-lane contiguous row read)
            const float4* srcW = (const float4*)(W + (size_t)t * Dn + d0);
            #pragma unroll
            for (int j = 0; j < 16; j++) {
                float4 v = srcW[j];
                uint2 u = make_uint2(h2u(__floats2half2_rn(v.x, v.y)),
                                     h2u(__floats2half2_rn(v.z, v.w)));
                *(uint2*)&B_s[t * 72 + j * 4] = u;
            }
        }
        __syncthreads();

        #pragma unroll
        for (int ks = 0; ks < 4; ks++) {
            int kb = ks * 16;
            unsigned a0 = *(const unsigned*)&A_s[(rw0 + g)     * 72 + kb + tg * 2];
            unsigned a1 = *(const unsigned*)&A_s[(rw0 + g + 8) * 72 + kb + tg * 2];
            unsigned a2 = *(const unsigned*)&A_s[(rw0 + g)     * 72 + kb + tg * 2 + 8];
            unsigned a3 = *(const unsigned*)&A_s[(rw0 + g + 8) * 72 + kb + tg * 2 + 8];
            #pragma unroll
            for (int nt = 0; nt < 16; nt++) {
                const __half* bp = &B_s[(h0w + nt * 8 + g) * 72 + kb + tg * 2];
                unsigned b0 = *(const unsigned*)bp;
                unsigned b1 = *(const unsigned*)(bp + 8);
                asm volatile(
                    "mma.sync.aligned.m16n8k16.row.col.f32.f16.f16.f32 "
                    "{%0,%1,%2,%3}, {%4,%5,%6,%7}, {%8,%9}, {%0,%1,%2,%3};"
                    : "+f"(c[nt][0]), "+f"(c[nt][1]), "+f"(c[nt][2]), "+f"(c[nt][3])
                    : "r"(a0), "r"(a1), "r"(a2), "r"(a3), "r"(b0), "r"(b1));
            }
        }
    }

    #pragma unroll
    for (int nt = 0; nt < 16; nt++) {
        int col = h0w + nt * 8 + tg * 2;
        *(unsigned*)&out[(size_t)(rw0 + g)     * Hn + col] =
            h2u(__floats2half2_rn(c[nt][0], c[nt][1]));
        *(unsigned*)&out[(size_t)(rw0 + g + 8) * Hn + col] =
            h2u(__floats2half2_rn(c[nt][2], c[nt][3]));
    }
}

// ============================================================
// Kernel 2: scores -> exp(score) via tanh.approx.f16x2 + EX2.
// No max subtraction: |score| <= ||w_v||_1 (~13), exp safely in fp32 range;
// numerator and denominator scale identically, so softmax is unchanged.
// Masked lanes in the boundary chunk store exact 0.
// grid = 4096 (b, qtile, k-chunk 32); early-exit fully-masked chunks.
// ============================================================
__global__ __launch_bounds__(256, 6) void score_kernel(
        const float* __restrict__ wv,
        const void*  __restrict__ vlens) {
    __shared__ __half2 s_kT2[128 * 33];   // [h2][32 k + pad]
    __shared__ __half2 s_q2[8 * 128];
    __shared__ __half2 s_wv2[128];

    int kc = blockIdx.x & 31;
    int qt = (blockIdx.x >> 5) & 15;
    int b  = blockIdx.x >> 9;
    int L  = decode_valid(vlens, b);
    int k0 = kc * 32;
    if (k0 >= L) return;               // uniform over block

    int t = threadIdx.x, w = t >> 5, l = t & 31;

    {   // transpose 32 k-rows (half) into s_kT2; conflict-free STS (stride 33)
        int kr = t >> 3, cg = t & 7;
        const uint4* src = (const uint4*)(g_kprojH + ((size_t)b * Kn + k0 + kr) * Hn);
        #pragma unroll
        for (int i = 0; i < 4; i++) {
            uint4 u = src[cg + i * 8];            // 8 halves = 4 h2
            int h2 = (cg + i * 8) * 4;
            s_kT2[(h2 + 0) * 33 + kr] = u2h(u.x);
            s_kT2[(h2 + 1) * 33 + kr] = u2h(u.y);
            s_kT2[(h2 + 2) * 33 + kr] = u2h(u.z);
            s_kT2[(h2 + 3) * 33 + kr] = u2h(u.w);
        }
    }
    {   // q tile: 8 rows x 512 B = 256 uint4
        const uint4* src = (const uint4*)(g_qprojH + ((size_t)b * Qn + qt * 8) * Hn);
        ((uint4*)s_q2)[t] = src[t];
    }
    if (t < 64) {   // w_v float -> half2 staging (prep kernel absorbed)
        float4 v = ((const float4*)wv)[t];
        s_wv2[t * 2]     = __floats2half2_rn(v.x, v.y);
        s_wv2[t * 2 + 1] = __floats2half2_rn(v.z, v.w);
    }
    __syncthreads();

    const uint4* q4 = (const uint4*)(s_q2 + (size_t)w * 128);
    const uint4* w4 = (const uint4*)s_wv2;
    float accx = 0.f, accy = 0.f;

    #pragma unroll 8
    for (int i = 0; i < 32; i++) {          // 8 h per iter
        uint4 qu = q4[i];                   // broadcast LDS.128 (4 h2)
        uint4 wu = w4[i];                   // broadcast LDS.128
        const __half2* kp = &s_kT2[(size_t)(i * 4) * 33 + l];
        unsigned x0, x1, x2, x3, t0, t1, t2, t3;
        __half2 h;
        h = __hadd2(u2h(qu.x), kp[0 * 33]); x0 = *(unsigned*)&h;
        h = __hadd2(u2h(qu.y), kp[1 * 33]); x1 = *(unsigned*)&h;
        h = __hadd2(u2h(qu.z), kp[2 * 33]); x2 = *(unsigned*)&h;
        h = __hadd2(u2h(qu.w), kp[3 * 33]); x3 = *(unsigned*)&h;
        asm("tanh.approx.f16x2 %0, %1;" : "=r"(t0) : "r"(x0));
        asm("tanh.approx.f16x2 %0, %1;" : "=r"(t1) : "r"(x1));
        asm("tanh.approx.f16x2 %0, %1;" : "=r"(t2) : "r"(x2));
        asm("tanh.approx.f16x2 %0, %1;" : "=r"(t3) : "r"(x3));
        __half2 p0 = __hmul2(u2h(wu.x), u2h(t0));
        __half2 p1 = __hmul2(u2h(wu.y), u2h(t1));
        __half2 p2 = __hmul2(u2h(wu.z), u2h(t2));
        __half2 p3 = __hmul2(u2h(wu.w), u2h(t3));
        __half2 s = __hadd2(__hadd2(p0, p1), __hadd2(p2, p3));
        float2 f = __half22float2(s);       // flush every 8 h -> fp32
        accx += f.x;
        accy += f.y;
    }
    float s = accx + accy;
    int kk = k0 + l;
    // store exp(score), exact 0 when masked -> av needs no mask logic
    g_scores[((size_t)b * Qn + qt * 8 + w) * Kn + kk] =
        (kk < L) ? __expf(s) : 0.f;
}

// ============================================================
// Kernel 3: out = (exp-weights @ V) / row-sum.  Softmax finalized in-flight.
// grid = B*16*4 = 512 (b, q-tile of 8, d-chunk of 64); block = 256.
// Stage 8 exp rows; warp-per-row sum -> 1/sum; FMA loop (MLP-8 k-batching);
// partials combined in smem; final scalar multiply by 1/sum.
// L==0: weights := 1 uniformly -> out = mean(V) (== reference softmax of
// all-masked). All k bounds multiples of 8; zeros beyond L make padding exact.
// ============================================================
__global__ __launch_bounds__(256) void av_kernel(
        const float* __restrict__ values,
        const void*  __restrict__ vlens,
        float* __restrict__ out) {
    __shared__ float s_attn[8][Kn];       // 32 KB
    __shared__ float s_part[4][8][64];    // 8 KB
    __shared__ float s_inv[8];

    int dc = blockIdx.x & 3;
    int qt = (blockIdx.x >> 2) & 15;
    int b  = blockIdx.x >> 6;
    int L  = decode_valid(vlens, b);
    int kEff = (L == 0) ? Kn : L;
    int t = threadIdx.x, w = t >> 5, l = t & 31;

    int kLim = (kEff + 7) & ~7;

    if (L == 0) {   // uniform weights (reference: softmax of all -1e9)
        float4 one = make_float4(1.f, 1.f, 1.f, 1.f);
        float4* dst = (float4*)&s_attn[0][0];
        #pragma unroll
        for (int i = 0; i < 8; i++)
            dst[t + i * 256] = one;
    } else {        // stage 8 exp rows coalesced
        const float4* src = (const float4*)(g_scores + ((size_t)(b * Qn + qt * 8)) * Kn);
        float4* dst = (float4*)&s_attn[0][0];
        #pragma unroll
        for (int i = 0; i < 8; i++)
            dst[t + i * 256] = src[t + i * 256];
    }
    __syncthreads();

    {   // row-sum -> 1/sum (warp w owns row w); [L, kLim) holds exact zeros
        float sum = 0.f;
        for (int k = l; k < kLim; k += 32)
            sum += s_attn[w][k];
        #pragma unroll
        for (int o = 16; o > 0; o >>= 1)
            sum += __shfl_xor_sync(0xffffffffu, sum, o);
        if (l == 0) s_inv[w] = 1.f / sum;
    }

    int dl = t & 63;                 // d within chunk
    int ks = t >> 6;                 // k-slice 0..3
    const float* vb = values + (size_t)b * Kn * Dn + dc * 64 + dl;

    int per = (((kLim >> 2) + 7) & ~7);       // per-slice span, multiple of 8
    int kb  = ks * per;
    int ke  = min(kb + per, kLim);

    float acc[8];
    #pragma unroll
    for (int qq = 0; qq < 8; qq++) acc[qq] = 0.f;

    for (int k = kb; k < ke; k += 8) {
        float v[8];
        #pragma unroll
        for (int j = 0; j < 8; j++)               // 8 LDGs batched: MLP 8
            v[j] = vb[(size_t)(k + j) * Dn];
        #pragma unroll
        for (int j = 0; j < 8; j += 4) {
            #pragma unroll
            for (int qq = 0; qq < 8; qq++) {
                float4 a = *(const float4*)&s_attn[qq][k + j];   // broadcast LDS.128
                acc[qq] = fmaf(a.x, v[j + 0], acc[qq]);
                acc[qq] = fmaf(a.y, v[j + 1], acc[qq]);
                acc[qq] = fmaf(a.z, v[j + 2], acc[qq]);
                acc[qq] = fmaf(a.w, v[j + 3], acc[qq]);
            }
        }
    }

    #pragma unroll
    for (int qq = 0; qq < 8; qq++) s_part[ks][qq][dl] = acc[qq];
    __syncthreads();   // also publishes s_inv

    for (int idx = t; idx < 512; idx += 256) {    // 8 q x 64 d outputs
        int q2  = idx >> 6;
        int dl2 = idx & 63;
        float s = s_part[0][q2][dl2] + s_part[1][q2][dl2] +
                  s_part[2][q2][dl2] + s_part[3][q2][dl2];
        out[((size_t)(b * Qn + qt * 8 + q2)) * Dn + dc * 64 + dl2] = s * s_inv[q2];
    }
}

// ============================================================
extern "C" void kernel_launch(void* const* d_in, const int* in_sizes, int n_in,
                              void* d_out, int out_size) {
    const float* queries = (const float*)d_in[0];
    const float* keys    = (const float*)d_in[1];
    const float* values  = (const float*)d_in[2];
    const float* Wq      = (const float*)d_in[3];
    const float* Wk      = (const float*)d_in[4];
    const float* wv      = (const float*)d_in[5];
    const void*  vlens   =               d_in[6];
    float* out = (float*)d_out;

    proj_kernel<<<(Bn * Qn + Bn * Kn) / 64, 256>>>(queries, keys, Wq, Wk, vlens);
    score_kernel<<<Bn * 16 * 32, 256>>>(wv, vlens);
    av_kernel<<<Bn * 16 * 4, 256>>>(values, vlens, out);
}